// round 13
// baseline (speedup 1.0000x reference)
#include <cuda_runtime.h>
#include <cstdint>

// Problem constants (fixed shapes from setup_inputs)
#define B_   512
#define C_   100
#define F_   224
#define E_   8192
#define H_   4
#define I_   28
#define INPUTS_ (F_ * I_)          // 6272 == x_b cols, no padding needed
#define FE_  (F_ * E_)             // 1,835,008
#define FE4_ (FE_ / 4)             // 458,752
#define BUILD_BLOCKS (FE4_ / 256)  // 1792
#define XWORDS_ (INPUTS_ / 32)     // 196
#define NSEG_ 4                    // accum f-segments
#define FSEG_ (F_ / NSEG_)         // 56 filters per segment
#define FWARP_ (FSEG_ / 8)         // 7 filters per warp

// Scratch (device globals: allocation-free per harness rules)
// negw[(f*E + e)] : uint4 whose bit c (across 4 words) set <=> table[c][f][e] < 0
__device__ __align__(64) uint32_t g_negw[F_ * E_ * 4];   // 29.36 MB, L2-resident
__device__ int4     g_hashes[B_ * F_];            // 1.8 MB
__device__ int      g_partial[NSEG_ * B_ * 128];  // 1 MB partial counts
// Per-(filter, 8-element sector) usage bitmap. Monotone OR of hash-derived
// bits; inputs are identical every replay so contents are deterministic
// without re-zeroing (zero-initialized at module load).
__device__ uint32_t g_used[F_ * (E_ / 8 / 32)];   // 224*32 = 7168 words

// 32-byte store with L2 evict-last policy (sm_103 requires .v4.b64 width for
// this modifier). Keeps negw resident in L2 through the table stream so the
// accum phase hits L2 instead of DRAM.
__device__ __forceinline__ void st32_evict_last(void* p,
                                                uint64_t q0, uint64_t q1,
                                                uint64_t q2, uint64_t q3) {
    asm volatile("st.global.L2::evict_last.v4.b64 [%0], {%1,%2,%3,%4};"
                 :: "l"(p), "l"(q0), "l"(q1), "l"(q2), "l"(q3) : "memory");
}

__device__ __forceinline__ uint64_t pk(uint32_t lo, uint32_t hi) {
    return (uint64_t)lo | ((uint64_t)hi << 32);
}

// ---------------------------------------------------------------------------
// Phase B: H3 hashes + used-sector marking. One block per batch row; x row
// ballot-packed into 196 smem words; thread f does 28 branchless conditional
// XORs for the 4 hash functions, then marks the 4 touched sectors of filter f
// in the global usage bitmap.
// ---------------------------------------------------------------------------
__global__ void __launch_bounds__(256)
hash_mark_kernel(const int* __restrict__ x_b,
                 const int* __restrict__ input_order,
                 const int* __restrict__ hash_values)
{
    __shared__ uint32_t s_xbits[XWORDS_];     // 784 B  (packed x row)
    __shared__ int      s_hv[H_ * I_];        // 448 B

    const int b    = blockIdx.x;
    const int tid  = threadIdx.x;
    const int wid  = tid >> 5;
    const int lane = tid & 31;

    // Ballot-pack the 6272-bit x row into 196 smem words.
    const int* xr = x_b + (size_t)b * INPUTS_;
    for (int j = wid; j < XWORDS_; j += 8) {
        int v = xr[j * 32 + lane];
        uint32_t bal = __ballot_sync(0xFFFFFFFFu, v != 0);
        if (lane == 0) s_xbits[j] = bal;
    }
    if (tid < H_ * I_)
        s_hv[tid] = hash_values[tid];
    __syncthreads();

    const int f = tid;
    if (f < F_) {
        const int* ord = input_order + f * I_;
        int h0 = 0, h1 = 0, h2 = 0, h3 = 0;
        #pragma unroll
        for (int i = 0; i < I_; ++i) {
            const int idx = __ldg(&ord[i]);
            const int m = -(int)((s_xbits[idx >> 5] >> (idx & 31)) & 1u);
            h0 ^= s_hv[0 * I_ + i] & m;
            h1 ^= s_hv[1 * I_ + i] & m;
            h2 ^= s_hv[2 * I_ + i] & m;
            h3 ^= s_hv[3 * I_ + i] & m;
        }
        g_hashes[b * F_ + f] = make_int4(h0, h1, h2, h3);

        // Mark used sectors: sector = h>>3, word = f*32 + (h>>8), bit = (h>>3)&31
        uint32_t* uf = g_used + f * 32;
        atomicOr(&uf[h0 >> 8], 1u << ((h0 >> 3) & 31));
        atomicOr(&uf[h1 >> 8], 1u << ((h1 >> 3) & 31));
        atomicOr(&uf[h2 >> 8], 1u << ((h2 >> 3) & 31));
        atomicOr(&uf[h3 >> 8], 1u << ((h3 >> 3) & 31));
    }
}

// ---------------------------------------------------------------------------
// Phase A: stream the table (coalesced float4, evict-first) and pack
// per-(f,e) 100-bit negative masks (stored evict-last, 2x32B per thread).
// Threads whose 32B sector is never hashed skip all 100 loads + stores,
// cutting ~13.5% of the 734MB DRAM stream.
// ---------------------------------------------------------------------------
__global__ void __launch_bounds__(256)
build_kernel(const float* __restrict__ table)
{
    const int t = blockIdx.x * 256 + threadIdx.x;     // 0 .. FE4_-1 (float4 units)
    // t = f*2048 + j  ->  bitmap word index = f*32 + (j>>6) = t>>6
    const uint32_t uw = __ldg(&g_used[t >> 6]);
    if (!((uw >> ((t >> 1) & 31)) & 1u))
        return;                                        // sector never consumed

    const float4* p = reinterpret_cast<const float4*>(table) + t;

    uint32_t a0[4] = {0,0,0,0};
    uint32_t a1[4] = {0,0,0,0};
    uint32_t a2[4] = {0,0,0,0};
    uint32_t a3[4] = {0,0,0,0};

    #pragma unroll
    for (int c = 0; c < C_; ++c) {
        float4 v = __ldcs(p + (size_t)c * FE4_);
        const uint32_t bit = 1u << (c & 31);
        const int w = c >> 5;                          // compile-time
        if (v.x < 0.0f) a0[w] |= bit;
        if (v.y < 0.0f) a1[w] |= bit;
        if (v.z < 0.0f) a2[w] |= bit;
        if (v.w < 0.0f) a3[w] |= bit;
    }

    char* out = reinterpret_cast<char*>(g_negw) + (size_t)t * 64;
    st32_evict_last(out,
                    pk(a0[0], a0[1]), pk(a0[2], a0[3]),
                    pk(a1[0], a1[1]), pk(a1[2], a1[3]));
    st32_evict_last(out + 32,
                    pk(a2[0], a2[1]), pk(a2[2], a2[3]),
                    pk(a3[0], a3[1]), pk(a3[2], a3[3]));
}

// ---------------------------------------------------------------------------
// Phase C: accumulate. Block = (batch row b, f-segment seg); 8 warps x 7
// filters each. The block's 56 hashes are staged in smem first (coalesced),
// so each loop iteration's gmem chain is ONE hop (4 independent warp-uniform
// uint4 loads — L2 hits thanks to evict-last negw). Partial class counts go
// to g_partial (deterministic, every slot written -> no init needed).
// ---------------------------------------------------------------------------
__global__ void __launch_bounds__(256)
accum_kernel()
{
    __shared__ int4 s_h[FSEG_];          // 56 staged hashes
    __shared__ int  s_cnt[8 * 132];

    const int b    = blockIdx.x;
    const int seg  = blockIdx.y;
    const int tid  = threadIdx.x;
    const int wi   = tid >> 5;
    const int lane = tid & 31;

    // Stage this block's hashes: 56 int4 = 224 ints, coalesced.
    const int* hsrc = reinterpret_cast<const int*>(g_hashes + b * F_ + seg * FSEG_);
    if (tid < FSEG_ * 4)
        reinterpret_cast<int*>(s_h)[tid] = __ldg(&hsrc[tid]);
    __syncthreads();

    const uint4* nw = reinterpret_cast<const uint4*>(g_negw);
    const int fbase = seg * FSEG_ + wi * FWARP_;

    int c0 = 0, c1 = 0, c2 = 0, c3 = 0;

    #pragma unroll
    for (int k = 0; k < FWARP_; ++k) {
        const int4 h = s_h[wi * FWARP_ + k];
        const uint4* base = nw + (size_t)(fbase + k) * E_;
        const uint4 ma = __ldg(&base[h.x]);
        const uint4 mb = __ldg(&base[h.y]);
        const uint4 mc = __ldg(&base[h.z]);
        const uint4 md = __ldg(&base[h.w]);
        const uint32_t mx = ma.x | mb.x | mc.x | md.x;
        const uint32_t my = ma.y | mb.y | mc.y | md.y;
        const uint32_t mz = ma.z | mb.z | mc.z | md.z;
        const uint32_t mw = ma.w | mb.w | mc.w | md.w;
        c0 += (mx >> lane) & 1;
        c1 += (my >> lane) & 1;
        c2 += (mz >> lane) & 1;
        c3 += (mw >> lane) & 1;
    }

    int* sr = s_cnt + wi * 132;
    sr[lane]      = c0;
    sr[lane + 32] = c1;
    sr[lane + 64] = c2;
    sr[lane + 96] = c3;
    __syncthreads();

    if (tid < 128) {
        int total = 0;
        #pragma unroll
        for (int w = 0; w < 8; ++w)
            total += s_cnt[w * 132 + tid];
        g_partial[(seg * B_ + b) * 128 + tid] = total;
    }
}

// ---------------------------------------------------------------------------
// Finalize: sum the NSEG_ partials per (b, c) and add bias.
// out[b][c] = bias[c] + F - 2 * count
// ---------------------------------------------------------------------------
__global__ void __launch_bounds__(128)
finalize_kernel(const float* __restrict__ bias, float* __restrict__ out)
{
    const int b   = blockIdx.x;
    const int tid = threadIdx.x;

    int total = 0;
    #pragma unroll
    for (int s = 0; s < NSEG_; ++s)
        total += g_partial[(s * B_ + b) * 128 + tid];

    if (tid < C_)
        out[b * C_ + tid] = bias[tid] + (float)(F_ - 2 * total);
}

// ---------------------------------------------------------------------------
// Launch. Input order per metadata: x_b, input_order, hash_values, table, bias
// ---------------------------------------------------------------------------
extern "C" void kernel_launch(void* const* d_in, const int* in_sizes, int n_in,
                              void* d_out, int out_size)
{
    const int*   x_b         = (const int*)  d_in[0];
    const int*   input_order = (const int*)  d_in[1];
    const int*   hash_values = (const int*)  d_in[2];
    const float* table       = (const float*)d_in[3];
    const float* bias        = (const float*)d_in[4];
    float*       out         = (float*)d_out;

    // Phase B: hashes + used-sector bitmap (must precede build)
    hash_mark_kernel<<<B_, 256>>>(x_b, input_order, hash_values);

    // Phase A: table stream -> sign masks, skipping never-used 32B sectors
    build_kernel<<<BUILD_BLOCKS, 256>>>(table);

    // Phase C: gather+accumulate from L2-resident negw
    accum_kernel<<<dim3(B_, NSEG_), 256>>>();

    // Combine partials + bias
    finalize_kernel<<<B_, 128>>>(bias, out);
}

// round 14
// speedup vs baseline: 1.0851x; 1.0851x over previous
#include <cuda_runtime.h>
#include <cstdint>

// Problem constants (fixed shapes from setup_inputs)
#define B_   512
#define C_   100
#define F_   224
#define E_   8192
#define H_   4
#define I_   28
#define INPUTS_ (F_ * I_)          // 6272 == x_b cols, no padding needed
#define FE_  (F_ * E_)             // 1,835,008
#define FE4_ (FE_ / 4)             // 458,752
#define BUILD_BLOCKS (FE4_ / 256)  // 1792
#define XWORDS_ (INPUTS_ / 32)     // 196
#define FWARP_ (F_ / 32)           // 7 filters per warp (32 warps/block)

// Scratch (device globals: allocation-free per harness rules)
// negw[(f*E + e)] : uint4 whose bit c (across 4 words) set <=> table[c][f][e] < 0
__device__ __align__(64) uint32_t g_negw[F_ * E_ * 4];   // 29.36 MB, L2-resident
__device__ int4     g_hashes[B_ * F_];            // 1.8 MB

// 32-byte store with L2 evict-last policy (sm_103 requires .v4.b64 width for
// this modifier). Keeps negw resident in L2 through the table stream so the
// accum phase hits L2 instead of DRAM.
__device__ __forceinline__ void st32_evict_last(void* p,
                                                uint64_t q0, uint64_t q1,
                                                uint64_t q2, uint64_t q3) {
    asm volatile("st.global.L2::evict_last.v4.b64 [%0], {%1,%2,%3,%4};"
                 :: "l"(p), "l"(q0), "l"(q1), "l"(q2), "l"(q3) : "memory");
}

__device__ __forceinline__ uint64_t pk(uint32_t lo, uint32_t hi) {
    return (uint64_t)lo | ((uint64_t)hi << 32);
}

// ---------------------------------------------------------------------------
// Fused Phase A + B. Blocks [0,BUILD_BLOCKS) stream the 734MB table
// (coalesced float4, evict-first) and pack per-(f,e) 100-bit negative masks
// (stored evict-last, 2x32B per thread). Blocks [BUILD_BLOCKS, +512) compute
// the H3 hashes for one batch row each, hiding under the build DRAM time.
// ---------------------------------------------------------------------------
__global__ void __launch_bounds__(256)
fused_build_hash_kernel(const float* __restrict__ table,
                        const int*   __restrict__ x_b,
                        const int*   __restrict__ input_order,
                        const int*   __restrict__ hash_values)
{
    __shared__ uint32_t s_xbits[XWORDS_];     // 784 B  (packed x row)
    __shared__ int      s_hv[H_ * I_];        // 448 B

    const int bid = blockIdx.x;

    if (bid < BUILD_BLOCKS) {
        // ---------------- build role ----------------
        const int t = bid * 256 + threadIdx.x;            // 0 .. FE4_-1
        const float4* p = reinterpret_cast<const float4*>(table) + t;

        uint32_t a0[4] = {0,0,0,0};
        uint32_t a1[4] = {0,0,0,0};
        uint32_t a2[4] = {0,0,0,0};
        uint32_t a3[4] = {0,0,0,0};

        #pragma unroll
        for (int c = 0; c < C_; ++c) {
            float4 v = __ldcs(p + (size_t)c * FE4_);
            const uint32_t bit = 1u << (c & 31);
            const int w = c >> 5;                         // compile-time
            if (v.x < 0.0f) a0[w] |= bit;
            if (v.y < 0.0f) a1[w] |= bit;
            if (v.z < 0.0f) a2[w] |= bit;
            if (v.w < 0.0f) a3[w] |= bit;
        }

        char* out = reinterpret_cast<char*>(g_negw) + (size_t)t * 64;
        st32_evict_last(out,
                        pk(a0[0], a0[1]), pk(a0[2], a0[3]),
                        pk(a1[0], a1[1]), pk(a1[2], a1[3]));
        st32_evict_last(out + 32,
                        pk(a2[0], a2[1]), pk(a2[2], a2[3]),
                        pk(a3[0], a3[1]), pk(a3[2], a3[3]));
    } else {
        // ---------------- hash role ----------------
        const int b    = bid - BUILD_BLOCKS;
        const int tid  = threadIdx.x;
        const int wid  = tid >> 5;
        const int lane = tid & 31;

        // Ballot-pack the 6272-bit x row into 196 smem words.
        const int* xr = x_b + (size_t)b * INPUTS_;
        for (int j = wid; j < XWORDS_; j += 8) {
            int v = xr[j * 32 + lane];
            uint32_t bal = __ballot_sync(0xFFFFFFFFu, v != 0);
            if (lane == 0) s_xbits[j] = bal;
        }
        if (tid < H_ * I_)
            s_hv[tid] = hash_values[tid];
        __syncthreads();

        const int f = tid;
        if (f < F_) {
            const int* ord = input_order + f * I_;
            int h0 = 0, h1 = 0, h2 = 0, h3 = 0;
            #pragma unroll
            for (int i = 0; i < I_; ++i) {
                const int idx = __ldg(&ord[i]);
                const int m = -(int)((s_xbits[idx >> 5] >> (idx & 31)) & 1u);
                h0 ^= s_hv[0 * I_ + i] & m;
                h1 ^= s_hv[1 * I_ + i] & m;
                h2 ^= s_hv[2 * I_ + i] & m;
                h3 ^= s_hv[3 * I_ + i] & m;
            }
            g_hashes[b * F_ + f] = make_int4(h0, h1, h2, h3);
        }
    }
}

// ---------------------------------------------------------------------------
// Phase C: accumulate + finalize in one kernel. Block = batch row b; 32 warps
// x 7 filters each (covers all F=224). The block's 224 hashes are staged in
// smem (coalesced), so each loop iteration's gmem chain is ONE hop (4
// independent warp-uniform uint4 loads — L2 hits thanks to evict-last negw).
// Warp partials reduced in smem; out written directly (no partial buffer, no
// finalize launch).
// out[b][c] = bias[c] + F - 2 * #{ f : OR_h negmask(f, hash_h) has bit c }
// ---------------------------------------------------------------------------
__global__ void __launch_bounds__(1024)
accum_kernel(const float* __restrict__ bias, float* __restrict__ out)
{
    __shared__ int4 s_h[F_];             // 224 staged hashes (3.5 KB)
    __shared__ int  s_cnt[32 * 132];     // 16.5 KB warp partials

    const int b    = blockIdx.x;
    const int tid  = threadIdx.x;
    const int wi   = tid >> 5;           // 0..31
    const int lane = tid & 31;

    // Stage this row's hashes: 224 int4 = 896 ints, coalesced.
    const int* hsrc = reinterpret_cast<const int*>(g_hashes + b * F_);
    if (tid < F_ * 4)
        reinterpret_cast<int*>(s_h)[tid] = __ldg(&hsrc[tid]);
    __syncthreads();

    const uint4* nw = reinterpret_cast<const uint4*>(g_negw);
    const int fbase = wi * FWARP_;

    int c0 = 0, c1 = 0, c2 = 0, c3 = 0;

    #pragma unroll
    for (int k = 0; k < FWARP_; ++k) {
        const int4 h = s_h[fbase + k];
        const uint4* base = nw + (size_t)(fbase + k) * E_;
        const uint4 ma = __ldg(&base[h.x]);
        const uint4 mb = __ldg(&base[h.y]);
        const uint4 mc = __ldg(&base[h.z]);
        const uint4 md = __ldg(&base[h.w]);
        const uint32_t mx = ma.x | mb.x | mc.x | md.x;
        const uint32_t my = ma.y | mb.y | mc.y | md.y;
        const uint32_t mz = ma.z | mb.z | mc.z | md.z;
        const uint32_t mw = ma.w | mb.w | mc.w | md.w;
        c0 += (mx >> lane) & 1;
        c1 += (my >> lane) & 1;
        c2 += (mz >> lane) & 1;
        c3 += (mw >> lane) & 1;
    }

    int* sr = s_cnt + wi * 132;
    sr[lane]      = c0;
    sr[lane + 32] = c1;
    sr[lane + 64] = c2;
    sr[lane + 96] = c3;
    __syncthreads();

    if (tid < 128) {
        int total = 0;
        #pragma unroll
        for (int w = 0; w < 32; ++w)
            total += s_cnt[w * 132 + tid];
        if (tid < C_)
            out[b * C_ + tid] = bias[tid] + (float)(F_ - 2 * total);
    }
}

// ---------------------------------------------------------------------------
// Launch. Input order per metadata: x_b, input_order, hash_values, table, bias
// ---------------------------------------------------------------------------
extern "C" void kernel_launch(void* const* d_in, const int* in_sizes, int n_in,
                              void* d_out, int out_size)
{
    const int*   x_b         = (const int*)  d_in[0];
    const int*   input_order = (const int*)  d_in[1];
    const int*   hash_values = (const int*)  d_in[2];
    const float* table       = (const float*)d_in[3];
    const float* bias        = (const float*)d_in[4];
    float*       out         = (float*)d_out;

    // Phase A+B fused: table stream + sign-mask build, hash blocks in the tail
    fused_build_hash_kernel<<<BUILD_BLOCKS + B_, 256>>>(
        table, x_b, input_order, hash_values);

    // Phase C: gather+accumulate from L2-resident negw, write out directly
    accum_kernel<<<B_, 1024>>>(bias, out);
}

// round 15
// speedup vs baseline: 1.1119x; 1.0247x over previous
#include <cuda_runtime.h>
#include <cstdint>

// Problem constants (fixed shapes from setup_inputs)
#define B_   512
#define C_   100
#define F_   224
#define E_   8192
#define H_   4
#define I_   28
#define INPUTS_ (F_ * I_)          // 6272 == x_b cols, no padding needed
#define FE_  (F_ * E_)             // 1,835,008
#define FE4_ (FE_ / 4)             // 458,752
#define BUILD_BLOCKS (FE4_ / 256)  // 1792
#define XWORDS_ (INPUTS_ / 32)     // 196
#define NSEG_ 7                    // accum f-segments
#define FSEG_ (F_ / NSEG_)         // 32 filters per segment
#define FWARP_ (FSEG_ / 8)         // 4 filters per warp

// Scratch (device globals: allocation-free per harness rules)
// negw[(f*E + e)] : uint4 whose bit c (across 4 words) set <=> table[c][f][e] < 0
__device__ __align__(64) uint32_t g_negw[F_ * E_ * 4];   // 29.36 MB
__device__ int4     g_hashes[B_ * F_];            // 1.8 MB

// 32-byte store with L2 evict-last policy (sm_103 requires .v4.b64 width for
// this modifier). Biases L2 toward keeping negw through the table stream.
__device__ __forceinline__ void st32_evict_last(void* p,
                                                uint64_t q0, uint64_t q1,
                                                uint64_t q2, uint64_t q3) {
    asm volatile("st.global.L2::evict_last.v4.b64 [%0], {%1,%2,%3,%4};"
                 :: "l"(p), "l"(q0), "l"(q1), "l"(q2), "l"(q3) : "memory");
}

__device__ __forceinline__ uint64_t pk(uint32_t lo, uint32_t hi) {
    return (uint64_t)lo | ((uint64_t)hi << 32);
}

// ---------------------------------------------------------------------------
// Fused Phase A + B. Blocks [0,BUILD_BLOCKS) stream the 734MB table
// (coalesced float4, evict-first) and pack per-(f,e) 100-bit negative masks
// (stored evict-last, 2x32B per thread). Blocks [BUILD_BLOCKS, +512) compute
// the H3 hashes for one batch row each AND initialize out[b][:] = bias + F,
// all hiding under the build blocks' DRAM time.
// ---------------------------------------------------------------------------
__global__ void __launch_bounds__(256)
fused_build_hash_kernel(const float* __restrict__ table,
                        const int*   __restrict__ x_b,
                        const int*   __restrict__ input_order,
                        const int*   __restrict__ hash_values,
                        const float* __restrict__ bias,
                        float*       __restrict__ out)
{
    __shared__ uint32_t s_xbits[XWORDS_];     // 784 B  (packed x row)
    __shared__ int      s_hv[H_ * I_];        // 448 B

    const int bid = blockIdx.x;

    if (bid < BUILD_BLOCKS) {
        // ---------------- build role ----------------
        const int t = bid * 256 + threadIdx.x;            // 0 .. FE4_-1
        const float4* p = reinterpret_cast<const float4*>(table) + t;

        uint32_t a0[4] = {0,0,0,0};
        uint32_t a1[4] = {0,0,0,0};
        uint32_t a2[4] = {0,0,0,0};
        uint32_t a3[4] = {0,0,0,0};

        #pragma unroll
        for (int c = 0; c < C_; ++c) {
            float4 v = __ldcs(p + (size_t)c * FE4_);
            const uint32_t bit = 1u << (c & 31);
            const int w = c >> 5;                         // compile-time
            if (v.x < 0.0f) a0[w] |= bit;
            if (v.y < 0.0f) a1[w] |= bit;
            if (v.z < 0.0f) a2[w] |= bit;
            if (v.w < 0.0f) a3[w] |= bit;
        }

        char* o = reinterpret_cast<char*>(g_negw) + (size_t)t * 64;
        st32_evict_last(o,
                        pk(a0[0], a0[1]), pk(a0[2], a0[3]),
                        pk(a1[0], a1[1]), pk(a1[2], a1[3]));
        st32_evict_last(o + 32,
                        pk(a2[0], a2[1]), pk(a2[2], a2[3]),
                        pk(a3[0], a3[1]), pk(a3[2], a3[3]));
    } else {
        // ---------------- hash + out-init role ----------------
        const int b    = bid - BUILD_BLOCKS;
        const int tid  = threadIdx.x;
        const int wid  = tid >> 5;
        const int lane = tid & 31;

        // Initialize out[b][:] = bias + F (accum blocks atomically subtract).
        if (tid < C_)
            out[b * C_ + tid] = bias[tid] + (float)F_;

        // Ballot-pack the 6272-bit x row into 196 smem words.
        const int* xr = x_b + (size_t)b * INPUTS_;
        for (int j = wid; j < XWORDS_; j += 8) {
            int v = xr[j * 32 + lane];
            uint32_t bal = __ballot_sync(0xFFFFFFFFu, v != 0);
            if (lane == 0) s_xbits[j] = bal;
        }
        if (tid < H_ * I_)
            s_hv[tid] = hash_values[tid];
        __syncthreads();

        const int f = tid;
        if (f < F_) {
            const int* ord = input_order + f * I_;
            int h0 = 0, h1 = 0, h2 = 0, h3 = 0;
            #pragma unroll
            for (int i = 0; i < I_; ++i) {
                const int idx = __ldg(&ord[i]);
                const int m = -(int)((s_xbits[idx >> 5] >> (idx & 31)) & 1u);
                h0 ^= s_hv[0 * I_ + i] & m;
                h1 ^= s_hv[1 * I_ + i] & m;
                h2 ^= s_hv[2 * I_ + i] & m;
                h3 ^= s_hv[3 * I_ + i] & m;
            }
            g_hashes[b * F_ + f] = make_int4(h0, h1, h2, h3);
        }
    }
}

// ---------------------------------------------------------------------------
// Phase C: accumulate. Block = (batch row b, f-segment seg); 8 warps x 4
// filters each (3584 blocks -> 28k independent warps, 4-hop load chains).
// The block's 32 hashes are staged in smem first, so each iteration's gmem
// chain is ONE hop (4 independent warp-uniform uint4 loads). Block partials
// are subtracted from out via atomicAdd of exact integer-valued floats
// (order-independent, deterministic; no finalize pass needed).
// out[b][c] = bias[c] + F - 2 * #{ f : OR_h negmask(f, hash_h) has bit c }
// ---------------------------------------------------------------------------
__global__ void __launch_bounds__(256)
accum_kernel(float* __restrict__ out)
{
    __shared__ int4 s_h[FSEG_];          // 32 staged hashes
    __shared__ int  s_cnt[8 * 132];

    const int b    = blockIdx.x;
    const int seg  = blockIdx.y;
    const int tid  = threadIdx.x;
    const int wi   = tid >> 5;
    const int lane = tid & 31;

    // Stage this block's hashes: 32 int4 = 128 ints, coalesced.
    const int* hsrc = reinterpret_cast<const int*>(g_hashes + b * F_ + seg * FSEG_);
    if (tid < FSEG_ * 4)
        reinterpret_cast<int*>(s_h)[tid] = __ldg(&hsrc[tid]);
    __syncthreads();

    const uint4* nw = reinterpret_cast<const uint4*>(g_negw);
    const int fbase = seg * FSEG_ + wi * FWARP_;

    int c0 = 0, c1 = 0, c2 = 0, c3 = 0;

    #pragma unroll
    for (int k = 0; k < FWARP_; ++k) {
        const int4 h = s_h[wi * FWARP_ + k];
        const uint4* base = nw + (size_t)(fbase + k) * E_;
        const uint4 ma = __ldg(&base[h.x]);
        const uint4 mb = __ldg(&base[h.y]);
        const uint4 mc = __ldg(&base[h.z]);
        const uint4 md = __ldg(&base[h.w]);
        const uint32_t mx = ma.x | mb.x | mc.x | md.x;
        const uint32_t my = ma.y | mb.y | mc.y | md.y;
        const uint32_t mz = ma.z | mb.z | mc.z | md.z;
        const uint32_t mw = ma.w | mb.w | mc.w | md.w;
        c0 += (mx >> lane) & 1;
        c1 += (my >> lane) & 1;
        c2 += (mz >> lane) & 1;
        c3 += (mw >> lane) & 1;
    }

    int* sr = s_cnt + wi * 132;
    sr[lane]      = c0;
    sr[lane + 32] = c1;
    sr[lane + 64] = c2;
    sr[lane + 96] = c3;
    __syncthreads();

    if (tid < C_) {
        int total = 0;
        #pragma unroll
        for (int w = 0; w < 8; ++w)
            total += s_cnt[w * 132 + tid];
        atomicAdd(&out[b * C_ + tid], (float)(-2 * total));
    }
}

// ---------------------------------------------------------------------------
// Launch. Input order per metadata: x_b, input_order, hash_values, table, bias
// ---------------------------------------------------------------------------
extern "C" void kernel_launch(void* const* d_in, const int* in_sizes, int n_in,
                              void* d_out, int out_size)
{
    const int*   x_b         = (const int*)  d_in[0];
    const int*   input_order = (const int*)  d_in[1];
    const int*   hash_values = (const int*)  d_in[2];
    const float* table       = (const float*)d_in[3];
    const float* bias        = (const float*)d_in[4];
    float*       out         = (float*)d_out;

    // Phase A+B fused: table stream + sign-mask build; hash blocks (which
    // also init out = bias + F) ride in the tail of the grid.
    fused_build_hash_kernel<<<BUILD_BLOCKS + B_, 256>>>(
        table, x_b, input_order, hash_values, bias, out);

    // Phase C: gather+accumulate, atomically folding partials into out
    accum_kernel<<<dim3(B_, NSEG_), 256>>>(out);
}